// round 4
// baseline (speedup 1.0000x reference)
#include <cuda_runtime.h>
#include <cuda_fp16.h>

// PointWarping2 — Nadaraya-Watson Gaussian regression.
// f32x2 FMA for the distance chain, fp16x2 ex2 (one MUFU per source-pair),
// fp16x2 HFMA2 accumulation with periodic f32 promotion, split-K + finalize.
//
// w = exp(-|q-y|^2/s^2) = 2^( L(2q·y - |y|^2) - L|q|^2 ),  L = log2(e)/s^2.
// arg computed in f32 (f32x2 per source pair), bias cn=-L|q|^2 added in fp16.

#define Bx 2
#define N1x 8192
#define N2x 8192
#define NQ (Bx * N2x)           // 16384 queries
#define MSPLIT 16
#define TILE 512                 // sources per split
#define PAIRS (TILE / 2)         // 256 source-pairs per tile
#define BLK 128
#define QPT 4                    // queries per thread
#define QPB (BLK * QPT)          // 512 queries per block
#define KCHUNK 32                // pairs per fp16 accumulation chunk

typedef unsigned long long ull;

__device__ float4 g_partial[MSPLIT * NQ];

__device__ __forceinline__ ull fma2(ull a, ull b, ull c) {
    ull d;
    asm("fma.rn.f32x2 %0, %1, %2, %3;" : "=l"(d) : "l"(a), "l"(b), "l"(c));
    return d;
}
__device__ __forceinline__ ull pack2(float lo, float hi) {
    ull d;
    asm("mov.b64 %0, {%1, %2};" : "=l"(d) : "f"(lo), "f"(hi));
    return d;
}
__device__ __forceinline__ void unpack2(ull v, float& lo, float& hi) {
    asm("mov.b64 {%0, %1}, %2;" : "=f"(lo), "=f"(hi) : "l"(v));
}
__device__ __forceinline__ half2 u2h2(unsigned u) {
    half2 h;
    *reinterpret_cast<unsigned*>(&h) = u;
    return h;
}

// resol_factor may arrive as int32 or float32 bits; disambiguate.
__device__ __forceinline__ float read_scale(const void* p) {
    int iv = *(const int*)p;
    float f;
    if (iv > 0 && iv < 100000) f = (float)iv;
    else f = __int_as_float(iv);
    return 1.0f * f;  // INITIAL_RADIUS = 1.0
}

__global__ __launch_bounds__(BLK) void main_kernel(
    const float* __restrict__ xyz1, const float* __restrict__ xyz2,
    const float* __restrict__ flow1, const void* __restrict__ resol) {
    __shared__ float4 sA[PAIRS];   // (ax0,ax1, ay0,ay1)  f32
    __shared__ float4 sB[PAIRS];   // (az0,az1, aw0,aw1)  f32
    __shared__ uint4  sF[PAIRS];   // (fx01, fy01, fz01, pad) half2 bits

    int qbase = blockIdx.x * QPB;           // block stays within one batch
    int b = qbase >> 13;
    float scale = read_scale(resol);
    float L = 1.4426950408889634f / (scale * scale);
    float t2 = 2.0f * L;

    // ---- fused prep: build packed source tile from raw inputs ----
    const float* x1b = xyz1 + b * 3 * N1x;
    const float* f1b = flow1 + b * 3 * N1x;
    int m0 = blockIdx.y * TILE;
    #pragma unroll
    for (int i = threadIdx.x; i < PAIRS; i += BLK) {
        int m = m0 + 2 * i;
        float2 xx = *(const float2*)(x1b + m);
        float2 xy = *(const float2*)(x1b + N1x + m);
        float2 xz = *(const float2*)(x1b + 2 * N1x + m);
        float2 fx = *(const float2*)(f1b + m);
        float2 fy = *(const float2*)(f1b + N1x + m);
        float2 fz = *(const float2*)(f1b + 2 * N1x + m);
        float yx0 = xx.x + fx.x, yx1 = xx.y + fx.y;
        float yy0 = xy.x + fy.x, yy1 = xy.y + fy.y;
        float yz0 = xz.x + fz.x, yz1 = xz.y + fz.y;
        sA[i] = make_float4(t2 * yx0, t2 * yx1, t2 * yy0, t2 * yy1);
        sB[i] = make_float4(t2 * yz0, t2 * yz1,
                            -L * (yx0 * yx0 + yy0 * yy0 + yz0 * yz0),
                            -L * (yx1 * yx1 + yy1 * yy1 + yz1 * yz1));
        half2 hx = __floats2half2_rn(fx.x, fx.y);
        half2 hy = __floats2half2_rn(fy.x, fy.y);
        half2 hz = __floats2half2_rn(fz.x, fz.y);
        sF[i] = make_uint4(*reinterpret_cast<unsigned*>(&hx),
                           *reinterpret_cast<unsigned*>(&hy),
                           *reinterpret_cast<unsigned*>(&hz), 0u);
    }

    // ---- query registers (QPT queries per thread) ----
    const float* x2b = xyz2 + b * 3 * N2x;
    ull qx2[QPT], qy2[QPT], qz2[QPT];
    half2 cnh[QPT];
    #pragma unroll
    for (int k = 0; k < QPT; k++) {
        int n = (qbase + threadIdx.x + k * BLK) & (N2x - 1);
        float qx = x2b[n], qy = x2b[N2x + n], qz = x2b[2 * N2x + n];
        qx2[k] = pack2(qx, qx);
        qy2[k] = pack2(qy, qy);
        qz2[k] = pack2(qz, qz);
        float cn = -L * (qx * qx + qy * qy + qz * qz);
        cnh[k] = __float2half2_rn(cn);
    }

    __syncthreads();

    const ulonglong2* uA = (const ulonglong2*)sA;
    const ulonglong2* uB = (const ulonglong2*)sB;

    float accx[QPT], accy[QPT], accz[QPT], accd[QPT];
    #pragma unroll
    for (int k = 0; k < QPT; k++) accx[k] = accy[k] = accz[k] = accd[k] = 0.f;

    for (int c0 = 0; c0 < PAIRS; c0 += KCHUNK) {
        half2 hxa[QPT], hya[QPT], hza[QPT], hda[QPT];
        half2 hzero = __floats2half2_rn(0.f, 0.f);
        #pragma unroll
        for (int k = 0; k < QPT; k++) { hxa[k] = hya[k] = hza[k] = hda[k] = hzero; }

        #pragma unroll 8
        for (int j = c0; j < c0 + KCHUNK; j++) {
            ulonglong2 a01 = uA[j];   // ax2, ay2
            ulonglong2 a23 = uB[j];   // az2, aw2
            uint4 fh = sF[j];
            half2 f_x = u2h2(fh.x);
            half2 f_y = u2h2(fh.y);
            half2 f_z = u2h2(fh.z);
            #pragma unroll
            for (int k = 0; k < QPT; k++) {
                ull t = fma2(qx2[k], a01.x,
                        fma2(qy2[k], a01.y,
                        fma2(qz2[k], a23.x, a23.y)));
                float lo, hi;
                unpack2(t, lo, hi);
                half2 ah = __floats2half2_rn(lo, hi);
                ah = __hadd2(ah, cnh[k]);
                half2 w = h2exp2(ah);
                hxa[k] = __hfma2(w, f_x, hxa[k]);
                hya[k] = __hfma2(w, f_y, hya[k]);
                hza[k] = __hfma2(w, f_z, hza[k]);
                hda[k] = __hadd2(hda[k], w);
            }
        }
        // promote chunk subtotals to f32
        #pragma unroll
        for (int k = 0; k < QPT; k++) {
            accx[k] += __low2float(hxa[k]) + __high2float(hxa[k]);
            accy[k] += __low2float(hya[k]) + __high2float(hya[k]);
            accz[k] += __low2float(hza[k]) + __high2float(hza[k]);
            accd[k] += __low2float(hda[k]) + __high2float(hda[k]);
        }
    }

    #pragma unroll
    for (int k = 0; k < QPT; k++) {
        int q = qbase + threadIdx.x + k * BLK;
        g_partial[blockIdx.y * NQ + q] =
            make_float4(accx[k], accy[k], accz[k], accd[k]);
    }
}

__global__ void finalize_kernel(const float* __restrict__ xyz2,
                                float* __restrict__ out) {
    int t = blockIdx.x * blockDim.x + threadIdx.x;   // 4 threads per query
    int q = t >> 2;
    int r = t & 3;
    if (q >= NQ) return;
    float nx = 0.f, ny = 0.f, nz = 0.f, den = 0.f;
    #pragma unroll
    for (int s = 0; s < MSPLIT / 4; s++) {
        float4 p = g_partial[(r + 4 * s) * NQ + q];
        nx += p.x; ny += p.y; nz += p.z; den += p.w;
    }
    #pragma unroll
    for (int d = 1; d < 4; d <<= 1) {
        nx  += __shfl_xor_sync(0xFFFFFFFFu, nx, d);
        ny  += __shfl_xor_sync(0xFFFFFFFFu, ny, d);
        nz  += __shfl_xor_sync(0xFFFFFFFFu, nz, d);
        den += __shfl_xor_sync(0xFFFFFFFFu, den, d);
    }
    if (r == 0) {
        int b = q >> 13;
        int n = q & (N2x - 1);
        float inv = 1.0f / den;
        const float* x2b = xyz2 + b * 3 * N2x;
        float* ob = out + b * 3 * N2x;
        ob[0 * N2x + n] = x2b[0 * N2x + n] - nx * inv;
        ob[1 * N2x + n] = x2b[1 * N2x + n] - ny * inv;
        ob[2 * N2x + n] = x2b[2 * N2x + n] - nz * inv;
    }
}

extern "C" void kernel_launch(void* const* d_in, const int* in_sizes, int n_in,
                              void* d_out, int out_size) {
    const float* xyz1  = (const float*)d_in[0];
    const float* xyz2  = (const float*)d_in[1];
    const float* flow1 = (const float*)d_in[2];
    const void*  resol = d_in[3];
    float* out = (float*)d_out;

    dim3 grid(NQ / QPB, MSPLIT);
    main_kernel<<<grid, BLK>>>(xyz1, xyz2, flow1, resol);

    finalize_kernel<<<(NQ * 4 + 255) / 256, 256>>>(xyz2, out);
}

// round 5
// speedup vs baseline: 1.2846x; 1.2846x over previous
#include <cuda_runtime.h>
#include <cuda_fp16.h>

// PointWarping2 — Nadaraya-Watson Gaussian regression (exact f32 math).
// Query-pair f32x2 packing: each fma.rn.f32x2 handles one source against TWO
// queries; sources are duplicated (a,a) in smem. One f32 MUFU ex2 per
// (src,query). Split-K (MSPLIT=32) + widened finalize.
//
// w' = ex2( q . a_xyz + a_w ), a = (2L*y, -L*|y|^2), L = log2(e)/s^2
// (per-query factor 2^{L|q|^2} cancels in num/den — exact).

#define Bx 2
#define N1x 8192
#define N2x 8192
#define NQ (Bx * N2x)           // 16384 queries
#define MSPLIT 32
#define TILE 256                 // sources per split
#define BLK 128
#define QPT 4                    // queries per thread (2 packed pairs)
#define QPB (BLK * QPT)          // 512 queries per block
#define HALFQ (QPB / 2)          // 256: offset between a thread's two pairs

typedef unsigned long long ull;

__device__ float4 g_partial[MSPLIT * NQ];

__device__ __forceinline__ float ex2f(float x) {
    float y;
    asm("ex2.approx.ftz.f32 %0, %1;" : "=f"(y) : "f"(x));
    return y;
}
__device__ __forceinline__ ull fma2(ull a, ull b, ull c) {
    ull d;
    asm("fma.rn.f32x2 %0, %1, %2, %3;" : "=l"(d) : "l"(a), "l"(b), "l"(c));
    return d;
}
__device__ __forceinline__ ull add2(ull a, ull b) {
    ull d;
    asm("add.rn.f32x2 %0, %1, %2;" : "=l"(d) : "l"(a), "l"(b));
    return d;
}
__device__ __forceinline__ ull pack2(float lo, float hi) {
    ull d;
    asm("mov.b64 %0, {%1, %2};" : "=l"(d) : "f"(lo), "f"(hi));
    return d;
}
__device__ __forceinline__ void unpack2(ull v, float& lo, float& hi) {
    asm("mov.b64 {%0, %1}, %2;" : "=f"(lo), "=f"(hi) : "l"(v));
}

// resol_factor may arrive as int32 or float32 bits; disambiguate.
__device__ __forceinline__ float read_scale(const void* p) {
    int iv = *(const int*)p;
    float f;
    if (iv > 0 && iv < 100000) f = (float)iv;
    else f = __int_as_float(iv);
    return 1.0f * f;  // INITIAL_RADIUS = 1.0
}

__global__ __launch_bounds__(BLK) void main_kernel(
    const float* __restrict__ xyz1, const float* __restrict__ xyz2,
    const float* __restrict__ flow1, const void* __restrict__ resol) {
    // duplicated source data: (ax,ax,ay,ay) (az,az,aw,aw) (fx,fx,fy,fy) (fz,fz)
    __shared__ float4 s0[TILE];
    __shared__ float4 s1[TILE];
    __shared__ float4 s2[TILE];
    __shared__ float2 s3[TILE];

    int qbase = blockIdx.x * QPB;           // block stays within one batch
    int b = qbase >> 13;
    float scale = read_scale(resol);
    float L = 1.4426950408889634f / (scale * scale);
    float t2 = 2.0f * L;

    // ---- fused prep: build duplicated source tile from raw inputs ----
    const float* x1b = xyz1 + b * 3 * N1x;
    const float* f1b = flow1 + b * 3 * N1x;
    int m0 = blockIdx.y * TILE;
    #pragma unroll
    for (int i = threadIdx.x; i < TILE; i += BLK) {
        int m = m0 + i;
        float fx = f1b[m], fy = f1b[N1x + m], fz = f1b[2 * N1x + m];
        float yx = x1b[m] + fx;
        float yy = x1b[N1x + m] + fy;
        float yz = x1b[2 * N1x + m] + fz;
        float ax = t2 * yx, ay = t2 * yy, az = t2 * yz;
        float aw = -L * (yx * yx + yy * yy + yz * yz);
        s0[i] = make_float4(ax, ax, ay, ay);
        s1[i] = make_float4(az, az, aw, aw);
        s2[i] = make_float4(fx, fx, fy, fy);
        s3[i] = make_float2(fz, fz);
    }

    // ---- query-pair registers: 2 pairs per thread ----
    const float* x2b = xyz2 + b * 3 * N2x;
    ull qx2[2], qy2[2], qz2[2];
    #pragma unroll
    for (int p = 0; p < 2; p++) {
        int n = ((qbase + 2 * threadIdx.x + p * HALFQ) & (N2x - 1));
        float2 vx = *(const float2*)(x2b + n);
        float2 vy = *(const float2*)(x2b + N2x + n);
        float2 vz = *(const float2*)(x2b + 2 * N2x + n);
        qx2[p] = pack2(vx.x, vx.y);
        qy2[p] = pack2(vy.x, vy.y);
        qz2[p] = pack2(vz.x, vz.y);
    }

    __syncthreads();

    const ulonglong2* u0 = (const ulonglong2*)s0;
    const ulonglong2* u1 = (const ulonglong2*)s1;
    const ulonglong2* u2 = (const ulonglong2*)s2;
    const ull*        u3 = (const ull*)s3;

    ull nx[2] = {0, 0}, ny[2] = {0, 0}, nz[2] = {0, 0}, dn[2] = {0, 0};

    #pragma unroll 8
    for (int j = 0; j < TILE; j++) {
        ulonglong2 a01 = u0[j];   // (ax,ax), (ay,ay)
        ulonglong2 a23 = u1[j];   // (az,az), (aw,aw)
        ulonglong2 f01 = u2[j];   // (fx,fx), (fy,fy)
        ull        fz2 = u3[j];   // (fz,fz)
        #pragma unroll
        for (int p = 0; p < 2; p++) {
            ull arg = fma2(qx2[p], a01.x,
                      fma2(qy2[p], a01.y,
                      fma2(qz2[p], a23.x, a23.y)));
            float lo, hi;
            unpack2(arg, lo, hi);
            ull w = pack2(ex2f(lo), ex2f(hi));
            nx[p] = fma2(w, f01.x, nx[p]);
            ny[p] = fma2(w, f01.y, ny[p]);
            nz[p] = fma2(w, fz2,   nz[p]);
            dn[p] = add2(dn[p], w);
        }
    }

    #pragma unroll
    for (int p = 0; p < 2; p++) {
        int q = qbase + 2 * threadIdx.x + p * HALFQ;
        float4 r0, r1;
        unpack2(nx[p], r0.x, r1.x);
        unpack2(ny[p], r0.y, r1.y);
        unpack2(nz[p], r0.z, r1.z);
        unpack2(dn[p], r0.w, r1.w);
        g_partial[blockIdx.y * NQ + q]     = r0;
        g_partial[blockIdx.y * NQ + q + 1] = r1;
    }
}

__global__ void finalize_kernel(const float* __restrict__ xyz2,
                                float* __restrict__ out) {
    int t = blockIdx.x * blockDim.x + threadIdx.x;   // 8 threads per query
    int q = t >> 3;
    int r = t & 7;
    if (q >= NQ) return;
    float nx = 0.f, ny = 0.f, nz = 0.f, den = 0.f;
    #pragma unroll
    for (int s = 0; s < MSPLIT / 8; s++) {
        float4 p = g_partial[(r + 8 * s) * NQ + q];
        nx += p.x; ny += p.y; nz += p.z; den += p.w;
    }
    #pragma unroll
    for (int d = 1; d < 8; d <<= 1) {
        nx  += __shfl_xor_sync(0xFFFFFFFFu, nx, d);
        ny  += __shfl_xor_sync(0xFFFFFFFFu, ny, d);
        nz  += __shfl_xor_sync(0xFFFFFFFFu, nz, d);
        den += __shfl_xor_sync(0xFFFFFFFFu, den, d);
    }
    if (r == 0) {
        int b = q >> 13;
        int n = q & (N2x - 1);
        float inv = 1.0f / den;
        const float* x2b = xyz2 + b * 3 * N2x;
        float* ob = out + b * 3 * N2x;
        ob[0 * N2x + n] = x2b[0 * N2x + n] - nx * inv;
        ob[1 * N2x + n] = x2b[1 * N2x + n] - ny * inv;
        ob[2 * N2x + n] = x2b[2 * N2x + n] - nz * inv;
    }
}

extern "C" void kernel_launch(void* const* d_in, const int* in_sizes, int n_in,
                              void* d_out, int out_size) {
    const float* xyz1  = (const float*)d_in[0];
    const float* xyz2  = (const float*)d_in[1];
    const float* flow1 = (const float*)d_in[2];
    const void*  resol = d_in[3];
    float* out = (float*)d_out;

    dim3 grid(NQ / QPB, MSPLIT);   // 32 x 32 = 1024 blocks, one wave
    main_kernel<<<grid, BLK>>>(xyz1, xyz2, flow1, resol);

    finalize_kernel<<<(NQ * 8 + 255) / 256, 256>>>(xyz2, out);
}